// round 1
// baseline (speedup 1.0000x reference)
#include <cuda_runtime.h>
#include <cuda_bf16.h>
#include <math.h>

// Problem constants
#define BB 32
#define TT 577
#define EE 1024
#define HH 16
#define DD 64
#define MM (BB * TT)   // 18464 rows

// Scratch (alloc-free rule: __device__ globals)
__device__ float g_q[(size_t)MM * EE];
__device__ float g_k[(size_t)MM * EE];
__device__ float g_v[(size_t)MM * EE];
__device__ float g_att[(size_t)MM * EE];

// ---------------------------------------------------------------------------
// SGEMM with bias: C[M,N] = A[M,K] @ B[K,N] + bias[N]
// BM=BN=128, BK=8, 256 threads, 8x8 register tile per thread.
// N and K assumed multiples of 128/8 (true here: 1024). M bounds-checked.
// ---------------------------------------------------------------------------
__global__ __launch_bounds__(256) void sgemm_bias_kernel(
    const float* __restrict__ A, const float* __restrict__ B,
    const float* __restrict__ bias, float* __restrict__ C,
    int M, int N, int K)
{
    constexpr int BM = 128, BN = 128, BK = 8, TM = 8, TN = 8;
    __shared__ float As[BK][BM];   // A tile stored transposed
    __shared__ float Bs[BK][BN];

    const int tid = threadIdx.x;
    const int tr = (tid >> 4) * TM;   // thread row offset in tile
    const int tc = (tid & 15) * TN;   // thread col offset in tile
    const int rowBase = blockIdx.y * BM;
    const int colBase = blockIdx.x * BN;

    // load mapping: A tile 128x8 -> 256 float4 (2 per row along K)
    const int aRow = tid >> 1;
    const int aCol = (tid & 1) * 4;
    // B tile 8x128 -> 256 float4
    const int bRow = tid >> 5;
    const int bCol = (tid & 31) * 4;

    float acc[TM][TN];
    #pragma unroll
    for (int i = 0; i < TM; i++)
        #pragma unroll
        for (int j = 0; j < TN; j++) acc[i][j] = 0.f;

    for (int k0 = 0; k0 < K; k0 += BK) {
        const int gRow = rowBase + aRow;
        float4 a4 = make_float4(0.f, 0.f, 0.f, 0.f);
        if (gRow < M)
            a4 = *(const float4*)(A + (size_t)gRow * K + k0 + aCol);
        As[aCol + 0][aRow] = a4.x;
        As[aCol + 1][aRow] = a4.y;
        As[aCol + 2][aRow] = a4.z;
        As[aCol + 3][aRow] = a4.w;

        float4 b4 = *(const float4*)(B + (size_t)(k0 + bRow) * N + colBase + bCol);
        *(float4*)&Bs[bRow][bCol] = b4;
        __syncthreads();

        #pragma unroll
        for (int kk = 0; kk < BK; kk++) {
            float ar[TM], br[TN];
            *(float4*)&ar[0] = *(const float4*)&As[kk][tr];
            *(float4*)&ar[4] = *(const float4*)&As[kk][tr + 4];
            *(float4*)&br[0] = *(const float4*)&Bs[kk][tc];
            *(float4*)&br[4] = *(const float4*)&Bs[kk][tc + 4];
            #pragma unroll
            for (int i = 0; i < TM; i++)
                #pragma unroll
                for (int j = 0; j < TN; j++)
                    acc[i][j] = fmaf(ar[i], br[j], acc[i][j]);
        }
        __syncthreads();
    }

    #pragma unroll
    for (int i = 0; i < TM; i++) {
        const int gRow = rowBase + tr + i;
        if (gRow < M) {
            #pragma unroll
            for (int j = 0; j < TN; j += 4) {
                const int gCol = colBase + tc + j;
                float4 o;
                o.x = acc[i][j + 0] + bias[gCol + 0];
                o.y = acc[i][j + 1] + bias[gCol + 1];
                o.z = acc[i][j + 2] + bias[gCol + 2];
                o.w = acc[i][j + 3] + bias[gCol + 3];
                *(float4*)(C + (size_t)gRow * N + gCol) = o;
            }
        }
    }
}

// ---------------------------------------------------------------------------
// Flash attention: per (b,h), per 64-query block. Key tiles of 32.
// q/k/v/o layouts: element (b,t,h,d) at ((b*T + t)*E + h*D + d), i.e. the
// natural [B,T,E] projection layout (no transpose materialization needed).
// ---------------------------------------------------------------------------
#define QB 64
#define KB 32

__global__ __launch_bounds__(256) void flash_attn_kernel(
    const float* __restrict__ q, const float* __restrict__ k,
    const float* __restrict__ v, float* __restrict__ o)
{
    const int bh = blockIdx.x;            // 0 .. B*H-1
    const int b = bh / HH;
    const int h = bh % HH;
    const int q0 = blockIdx.y * QB;

    const size_t base = (size_t)b * TT * EE + (size_t)h * DD;
    const float* Q = q + base;
    const float* K = k + base;
    const float* V = v + base;
    float* O = o + base;

    __shared__ float Qs[QB][DD + 4];   // stride 68
    __shared__ float Ks[KB][DD + 1];   // stride 65 (odd -> conflict-free row access)
    __shared__ float Vs[KB][DD + 4];   // stride 68
    __shared__ float Ps[QB][KB + 4];   // stride 36
    __shared__ float m_s[QB], l_s[QB], c_s[QB];

    const int tid = threadIdx.x;       // 256
    const int ty = tid >> 4;           // 0..15
    const int tx = tid & 15;           // 0..15

    // Load Q tile: 64 rows x 16 float4/row = 1024 float4, 4 per thread
    #pragma unroll
    for (int i = 0; i < 4; i++) {
        const int idx = tid + i * 256;
        const int r = idx >> 4;
        const int c4 = (idx & 15) << 2;
        const int gr = q0 + r;
        float4 val = make_float4(0.f, 0.f, 0.f, 0.f);
        if (gr < TT) val = *(const float4*)(Q + (size_t)gr * EE + c4);
        *(float4*)&Qs[r][c4] = val;
    }
    if (tid < QB) { m_s[tid] = -1e30f; l_s[tid] = 0.f; }

    float o_acc[4][4];
    #pragma unroll
    for (int a = 0; a < 4; a++)
        #pragma unroll
        for (int bb = 0; bb < 4; bb++) o_acc[a][bb] = 0.f;

    const int nkt = (TT + KB - 1) / KB;   // 19
    for (int kt = 0; kt < nkt; kt++) {
        __syncthreads();   // previous tile's Ps/Vs reads done; Qs visible (iter 0)

        // Load K,V tile: 32 rows x 16 float4 = 512 float4 each, 2 per thread
        #pragma unroll
        for (int i = 0; i < 2; i++) {
            const int idx = tid + i * 256;
            const int r = idx >> 4;
            const int c4 = (idx & 15) << 2;
            const int gr = kt * KB + r;
            float4 kv = make_float4(0.f, 0.f, 0.f, 0.f);
            float4 vv = make_float4(0.f, 0.f, 0.f, 0.f);
            if (gr < TT) {
                kv = *(const float4*)(K + (size_t)gr * EE + c4);
                vv = *(const float4*)(V + (size_t)gr * EE + c4);
            }
            Ks[r][c4 + 0] = kv.x; Ks[r][c4 + 1] = kv.y;
            Ks[r][c4 + 2] = kv.z; Ks[r][c4 + 3] = kv.w;
            *(float4*)&Vs[r][c4] = vv;
        }
        __syncthreads();

        // Scores: thread covers q rows ty*4+a (a<4), k cols tx*2+b (b<2)
        float s[4][2];
        #pragma unroll
        for (int a = 0; a < 4; a++) { s[a][0] = 0.f; s[a][1] = 0.f; }

        #pragma unroll 8
        for (int d = 0; d < DD; d++) {
            float kv0 = Ks[tx * 2 + 0][d];
            float kv1 = Ks[tx * 2 + 1][d];
            #pragma unroll
            for (int a = 0; a < 4; a++) {
                const float qv = Qs[ty * 4 + a][d];
                s[a][0] = fmaf(qv, kv0, s[a][0]);
                s[a][1] = fmaf(qv, kv1, s[a][1]);
            }
        }

        // Scale + mask + per-thread row max
        float tmax[4];
        #pragma unroll
        for (int a = 0; a < 4; a++) {
            tmax[a] = -1e30f;
            #pragma unroll
            for (int bb = 0; bb < 2; bb++) {
                const int kc = kt * KB + tx * 2 + bb;
                s[a][bb] = (kc < TT) ? s[a][bb] * 0.125f : -1e30f;
                tmax[a] = fmaxf(tmax[a], s[a][bb]);
            }
        }
        // Reduce max over the 16 tx lanes (lanes (ty&1)*16 + tx: xor 1,2,4,8
        // stays inside the 16-lane group)
        #pragma unroll
        for (int off = 8; off > 0; off >>= 1)
            #pragma unroll
            for (int a = 0; a < 4; a++)
                tmax[a] = fmaxf(tmax[a], __shfl_xor_sync(0xffffffffu, tmax[a], off));

        if (tx == 0) {
            #pragma unroll
            for (int a = 0; a < 4; a++) {
                const int r = ty * 4 + a;
                const float mo = m_s[r];
                const float mn = fmaxf(mo, tmax[a]);
                c_s[r] = __expf(mo - mn);
                m_s[r] = mn;
            }
        }
        __syncthreads();

        // P = exp(s - m), row sums, write P to smem
        float rs[4];
        #pragma unroll
        for (int a = 0; a < 4; a++) {
            const int r = ty * 4 + a;
            const float mrow = m_s[r];
            float p0 = __expf(s[a][0] - mrow);
            float p1 = __expf(s[a][1] - mrow);
            Ps[r][tx * 2 + 0] = p0;
            Ps[r][tx * 2 + 1] = p1;
            rs[a] = p0 + p1;
        }
        #pragma unroll
        for (int off = 8; off > 0; off >>= 1)
            #pragma unroll
            for (int a = 0; a < 4; a++)
                rs[a] += __shfl_xor_sync(0xffffffffu, rs[a], off);
        if (tx == 0) {
            #pragma unroll
            for (int a = 0; a < 4; a++) {
                const int r = ty * 4 + a;
                l_s[r] = l_s[r] * c_s[r] + rs[a];
            }
        }
        // Rescale O accumulator by correction factor
        #pragma unroll
        for (int a = 0; a < 4; a++) {
            const float c = c_s[ty * 4 + a];
            #pragma unroll
            for (int bb = 0; bb < 4; bb++) o_acc[a][bb] *= c;
        }
        __syncthreads();   // Ps complete

        // O += P @ V : thread covers q rows ty*4+a, d cols tx*4+b
        #pragma unroll 8
        for (int kk = 0; kk < KB; kk++) {
            float vv[4];
            #pragma unroll
            for (int bb = 0; bb < 4; bb++) vv[bb] = Vs[kk][tx * 4 + bb];
            #pragma unroll
            for (int a = 0; a < 4; a++) {
                const float pv = Ps[ty * 4 + a][kk];
                #pragma unroll
                for (int bb = 0; bb < 4; bb++)
                    o_acc[a][bb] = fmaf(pv, vv[bb], o_acc[a][bb]);
            }
        }
    }
    __syncthreads();

    // Epilogue: normalize and store
    #pragma unroll
    for (int a = 0; a < 4; a++) {
        const int r = ty * 4 + a;
        const int gr = q0 + r;
        if (gr < TT) {
            const float inv = 1.f / l_s[r];
            float4 ov;
            ov.x = o_acc[a][0] * inv;
            ov.y = o_acc[a][1] * inv;
            ov.z = o_acc[a][2] * inv;
            ov.w = o_acc[a][3] * inv;
            *(float4*)(O + (size_t)gr * EE + tx * 4) = ov;
        }
    }
}

// ---------------------------------------------------------------------------
// Launch
// ---------------------------------------------------------------------------
extern "C" void kernel_launch(void* const* d_in, const int* in_sizes, int n_in,
                              void* d_out, int out_size)
{
    const float* x  = (const float*)d_in[0];
    const float* Wq = (const float*)d_in[1];
    const float* bq = (const float*)d_in[2];
    const float* Wk = (const float*)d_in[3];
    const float* bk = (const float*)d_in[4];
    const float* Wv = (const float*)d_in[5];
    const float* bv = (const float*)d_in[6];
    const float* Wo = (const float*)d_in[7];
    const float* bo = (const float*)d_in[8];
    float* out = (float*)d_out;

    float *gq, *gk, *gv, *ga;
    cudaGetSymbolAddress((void**)&gq, g_q);
    cudaGetSymbolAddress((void**)&gk, g_k);
    cudaGetSymbolAddress((void**)&gv, g_v);
    cudaGetSymbolAddress((void**)&ga, g_att);

    dim3 gridG(EE / 128, (MM + 127) / 128);   // (8, 145)
    sgemm_bias_kernel<<<gridG, 256>>>(x, Wq, bq, gq, MM, EE, EE);
    sgemm_bias_kernel<<<gridG, 256>>>(x, Wk, bk, gk, MM, EE, EE);
    sgemm_bias_kernel<<<gridG, 256>>>(x, Wv, bv, gv, MM, EE, EE);

    dim3 gridA(BB * HH, (TT + QB - 1) / QB);  // (512, 10)
    flash_attn_kernel<<<gridA, 256>>>(gq, gk, gv, ga);

    sgemm_bias_kernel<<<gridG, 256>>>(ga, Wo, bo, out, MM, EE, EE);
}

// round 2
// speedup vs baseline: 1.0009x; 1.0009x over previous
#include <cuda_runtime.h>
#include <cuda_bf16.h>
#include <math.h>

// Problem constants
#define BB 32
#define TT 577
#define EE 1024
#define HH 16
#define DD 64
#define MM (BB * TT)   // 18464 rows

// Scratch (alloc-free rule: __device__ globals)
__device__ float g_q[(size_t)MM * EE];
__device__ float g_k[(size_t)MM * EE];
__device__ float g_v[(size_t)MM * EE];
__device__ float g_att[(size_t)MM * EE];

// ---------------------------------------------------------------------------
// SGEMM with bias: C[M,N] = A[M,K] @ B[K,N] + bias[N]
// BM=BN=128, BK=8, 256 threads, 8x8 register tile per thread.
// N and K assumed multiples of 128/8 (true here: 1024). M bounds-checked.
// ---------------------------------------------------------------------------
__global__ __launch_bounds__(256) void sgemm_bias_kernel(
    const float* __restrict__ A, const float* __restrict__ B,
    const float* __restrict__ bias, float* __restrict__ C,
    int M, int N, int K)
{
    constexpr int BM = 128, BN = 128, BK = 8, TM = 8, TN = 8;
    __shared__ float As[BK][BM];   // A tile stored transposed
    __shared__ float Bs[BK][BN];

    const int tid = threadIdx.x;
    const int tr = (tid >> 4) * TM;   // thread row offset in tile
    const int tc = (tid & 15) * TN;   // thread col offset in tile
    const int rowBase = blockIdx.y * BM;
    const int colBase = blockIdx.x * BN;

    // load mapping: A tile 128x8 -> 256 float4 (2 per row along K)
    const int aRow = tid >> 1;
    const int aCol = (tid & 1) * 4;
    // B tile 8x128 -> 256 float4
    const int bRow = tid >> 5;
    const int bCol = (tid & 31) * 4;

    float acc[TM][TN];
    #pragma unroll
    for (int i = 0; i < TM; i++)
        #pragma unroll
        for (int j = 0; j < TN; j++) acc[i][j] = 0.f;

    for (int k0 = 0; k0 < K; k0 += BK) {
        const int gRow = rowBase + aRow;
        float4 a4 = make_float4(0.f, 0.f, 0.f, 0.f);
        if (gRow < M)
            a4 = *(const float4*)(A + (size_t)gRow * K + k0 + aCol);
        As[aCol + 0][aRow] = a4.x;
        As[aCol + 1][aRow] = a4.y;
        As[aCol + 2][aRow] = a4.z;
        As[aCol + 3][aRow] = a4.w;

        float4 b4 = *(const float4*)(B + (size_t)(k0 + bRow) * N + colBase + bCol);
        *(float4*)&Bs[bRow][bCol] = b4;
        __syncthreads();

        #pragma unroll
        for (int kk = 0; kk < BK; kk++) {
            float ar[TM], br[TN];
            *(float4*)&ar[0] = *(const float4*)&As[kk][tr];
            *(float4*)&ar[4] = *(const float4*)&As[kk][tr + 4];
            *(float4*)&br[0] = *(const float4*)&Bs[kk][tc];
            *(float4*)&br[4] = *(const float4*)&Bs[kk][tc + 4];
            #pragma unroll
            for (int i = 0; i < TM; i++)
                #pragma unroll
                for (int j = 0; j < TN; j++)
                    acc[i][j] = fmaf(ar[i], br[j], acc[i][j]);
        }
        __syncthreads();
    }

    #pragma unroll
    for (int i = 0; i < TM; i++) {
        const int gRow = rowBase + tr + i;
        if (gRow < M) {
            #pragma unroll
            for (int j = 0; j < TN; j += 4) {
                const int gCol = colBase + tc + j;
                float4 o;
                o.x = acc[i][j + 0] + bias[gCol + 0];
                o.y = acc[i][j + 1] + bias[gCol + 1];
                o.z = acc[i][j + 2] + bias[gCol + 2];
                o.w = acc[i][j + 3] + bias[gCol + 3];
                *(float4*)(C + (size_t)gRow * N + gCol) = o;
            }
        }
    }
}

// ---------------------------------------------------------------------------
// Flash attention: per (b,h), per 64-query block. Key tiles of 32.
// q/k/v/o layouts: element (b,t,h,d) at ((b*T + t)*E + h*D + d), i.e. the
// natural [B,T,E] projection layout (no transpose materialization needed).
// ---------------------------------------------------------------------------
#define QB 64
#define KB 32

__global__ __launch_bounds__(256) void flash_attn_kernel(
    const float* __restrict__ q, const float* __restrict__ k,
    const float* __restrict__ v, float* __restrict__ o)
{
    const int bh = blockIdx.x;            // 0 .. B*H-1
    const int b = bh / HH;
    const int h = bh % HH;
    const int q0 = blockIdx.y * QB;

    const size_t base = (size_t)b * TT * EE + (size_t)h * DD;
    const float* Q = q + base;
    const float* K = k + base;
    const float* V = v + base;
    float* O = o + base;

    __shared__ float Qs[QB][DD + 4];   // stride 68
    __shared__ float Ks[KB][DD + 1];   // stride 65 (odd -> conflict-free row access)
    __shared__ float Vs[KB][DD + 4];   // stride 68
    __shared__ float Ps[QB][KB + 4];   // stride 36
    __shared__ float m_s[QB], l_s[QB], c_s[QB];

    const int tid = threadIdx.x;       // 256
    const int ty = tid >> 4;           // 0..15
    const int tx = tid & 15;           // 0..15

    // Load Q tile: 64 rows x 16 float4/row = 1024 float4, 4 per thread
    #pragma unroll
    for (int i = 0; i < 4; i++) {
        const int idx = tid + i * 256;
        const int r = idx >> 4;
        const int c4 = (idx & 15) << 2;
        const int gr = q0 + r;
        float4 val = make_float4(0.f, 0.f, 0.f, 0.f);
        if (gr < TT) val = *(const float4*)(Q + (size_t)gr * EE + c4);
        *(float4*)&Qs[r][c4] = val;
    }
    if (tid < QB) { m_s[tid] = -1e30f; l_s[tid] = 0.f; }

    float o_acc[4][4];
    #pragma unroll
    for (int a = 0; a < 4; a++)
        #pragma unroll
        for (int bb = 0; bb < 4; bb++) o_acc[a][bb] = 0.f;

    const int nkt = (TT + KB - 1) / KB;   // 19
    for (int kt = 0; kt < nkt; kt++) {
        __syncthreads();   // previous tile's Ps/Vs reads done; Qs visible (iter 0)

        // Load K,V tile: 32 rows x 16 float4 = 512 float4 each, 2 per thread
        #pragma unroll
        for (int i = 0; i < 2; i++) {
            const int idx = tid + i * 256;
            const int r = idx >> 4;
            const int c4 = (idx & 15) << 2;
            const int gr = kt * KB + r;
            float4 kv = make_float4(0.f, 0.f, 0.f, 0.f);
            float4 vv = make_float4(0.f, 0.f, 0.f, 0.f);
            if (gr < TT) {
                kv = *(const float4*)(K + (size_t)gr * EE + c4);
                vv = *(const float4*)(V + (size_t)gr * EE + c4);
            }
            Ks[r][c4 + 0] = kv.x; Ks[r][c4 + 1] = kv.y;
            Ks[r][c4 + 2] = kv.z; Ks[r][c4 + 3] = kv.w;
            *(float4*)&Vs[r][c4] = vv;
        }
        __syncthreads();

        // Scores: thread covers q rows ty*4+a (a<4), k cols tx*2+b (b<2)
        float s[4][2];
        #pragma unroll
        for (int a = 0; a < 4; a++) { s[a][0] = 0.f; s[a][1] = 0.f; }

        #pragma unroll 8
        for (int d = 0; d < DD; d++) {
            float kv0 = Ks[tx * 2 + 0][d];
            float kv1 = Ks[tx * 2 + 1][d];
            #pragma unroll
            for (int a = 0; a < 4; a++) {
                const float qv = Qs[ty * 4 + a][d];
                s[a][0] = fmaf(qv, kv0, s[a][0]);
                s[a][1] = fmaf(qv, kv1, s[a][1]);
            }
        }

        // Scale + mask + per-thread row max
        float tmax[4];
        #pragma unroll
        for (int a = 0; a < 4; a++) {
            tmax[a] = -1e30f;
            #pragma unroll
            for (int bb = 0; bb < 2; bb++) {
                const int kc = kt * KB + tx * 2 + bb;
                s[a][bb] = (kc < TT) ? s[a][bb] * 0.125f : -1e30f;
                tmax[a] = fmaxf(tmax[a], s[a][bb]);
            }
        }
        // Reduce max over the 16 tx lanes (lanes (ty&1)*16 + tx: xor 1,2,4,8
        // stays inside the 16-lane group)
        #pragma unroll
        for (int off = 8; off > 0; off >>= 1)
            #pragma unroll
            for (int a = 0; a < 4; a++)
                tmax[a] = fmaxf(tmax[a], __shfl_xor_sync(0xffffffffu, tmax[a], off));

        if (tx == 0) {
            #pragma unroll
            for (int a = 0; a < 4; a++) {
                const int r = ty * 4 + a;
                const float mo = m_s[r];
                const float mn = fmaxf(mo, tmax[a]);
                c_s[r] = __expf(mo - mn);
                m_s[r] = mn;
            }
        }
        __syncthreads();

        // P = exp(s - m), row sums, write P to smem
        float rs[4];
        #pragma unroll
        for (int a = 0; a < 4; a++) {
            const int r = ty * 4 + a;
            const float mrow = m_s[r];
            float p0 = __expf(s[a][0] - mrow);
            float p1 = __expf(s[a][1] - mrow);
            Ps[r][tx * 2 + 0] = p0;
            Ps[r][tx * 2 + 1] = p1;
            rs[a] = p0 + p1;
        }
        #pragma unroll
        for (int off = 8; off > 0; off >>= 1)
            #pragma unroll
            for (int a = 0; a < 4; a++)
                rs[a] += __shfl_xor_sync(0xffffffffu, rs[a], off);
        if (tx == 0) {
            #pragma unroll
            for (int a = 0; a < 4; a++) {
                const int r = ty * 4 + a;
                l_s[r] = l_s[r] * c_s[r] + rs[a];
            }
        }
        // Rescale O accumulator by correction factor
        #pragma unroll
        for (int a = 0; a < 4; a++) {
            const float c = c_s[ty * 4 + a];
            #pragma unroll
            for (int bb = 0; bb < 4; bb++) o_acc[a][bb] *= c;
        }
        __syncthreads();   // Ps complete

        // O += P @ V : thread covers q rows ty*4+a, d cols tx*4+b
        #pragma unroll 8
        for (int kk = 0; kk < KB; kk++) {
            float vv[4];
            #pragma unroll
            for (int bb = 0; bb < 4; bb++) vv[bb] = Vs[kk][tx * 4 + bb];
            #pragma unroll
            for (int a = 0; a < 4; a++) {
                const float pv = Ps[ty * 4 + a][kk];
                #pragma unroll
                for (int bb = 0; bb < 4; bb++)
                    o_acc[a][bb] = fmaf(pv, vv[bb], o_acc[a][bb]);
            }
        }
    }
    __syncthreads();

    // Epilogue: normalize and store
    #pragma unroll
    for (int a = 0; a < 4; a++) {
        const int r = ty * 4 + a;
        const int gr = q0 + r;
        if (gr < TT) {
            const float inv = 1.f / l_s[r];
            float4 ov;
            ov.x = o_acc[a][0] * inv;
            ov.y = o_acc[a][1] * inv;
            ov.z = o_acc[a][2] * inv;
            ov.w = o_acc[a][3] * inv;
            *(float4*)(O + (size_t)gr * EE + tx * 4) = ov;
        }
    }
}

// ---------------------------------------------------------------------------
// Launch
// ---------------------------------------------------------------------------
extern "C" void kernel_launch(void* const* d_in, const int* in_sizes, int n_in,
                              void* d_out, int out_size)
{
    const float* x  = (const float*)d_in[0];
    const float* Wq = (const float*)d_in[1];
    const float* bq = (const float*)d_in[2];
    const float* Wk = (const float*)d_in[3];
    const float* bk = (const float*)d_in[4];
    const float* Wv = (const float*)d_in[5];
    const float* bv = (const float*)d_in[6];
    const float* Wo = (const float*)d_in[7];
    const float* bo = (const float*)d_in[8];
    float* out = (float*)d_out;

    float *gq, *gk, *gv, *ga;
    cudaGetSymbolAddress((void**)&gq, g_q);
    cudaGetSymbolAddress((void**)&gk, g_k);
    cudaGetSymbolAddress((void**)&gv, g_v);
    cudaGetSymbolAddress((void**)&ga, g_att);

    dim3 gridG(EE / 128, (MM + 127) / 128);   // (8, 145)
    sgemm_bias_kernel<<<gridG, 256>>>(x, Wq, bq, gq, MM, EE, EE);
    sgemm_bias_kernel<<<gridG, 256>>>(x, Wk, bk, gk, MM, EE, EE);
    sgemm_bias_kernel<<<gridG, 256>>>(x, Wv, bv, gv, MM, EE, EE);

    dim3 gridA(BB * HH, (TT + QB - 1) / QB);  // (512, 10)
    flash_attn_kernel<<<gridA, 256>>>(gq, gk, gv, ga);

    sgemm_bias_kernel<<<gridG, 256>>>(ga, Wo, bo, out, MM, EE, EE);
}